// round 12
// baseline (speedup 1.0000x reference)
#include <cuda_runtime.h>
#include <cuda_bf16.h>
#include <math.h>

#define NMAX 50000
#define EMAX 1600000
#define DMODEL 256
#define NHEAD 8
#define HD 32

// ---------------- scratch (static device globals; no allocation) -------------
__device__ float g_xn  [(size_t)NMAX * DMODEL];
__device__ float g_q   [(size_t)NMAX * DMODEL];
__device__ float g_k   [(size_t)NMAX * DMODEL];
__device__ float g_v   [(size_t)NMAX * DMODEL];
__device__ float g_qw  [(size_t)NMAX * DMODEL];
__device__ float g_qbe [(size_t)NMAX * NHEAD];
__device__ float g_Wqw [DMODEL * DMODEL];
__device__ float g_bqw [DMODEL];
__device__ float g_sc  [(size_t)NHEAD * EMAX];
__device__ float g_agg [(size_t)NMAX * DMODEL];
__device__ float g_x1  [(size_t)NMAX * DMODEL];
__device__ float g_xn2 [(size_t)NMAX * DMODEL];
__device__ float g_ff  [(size_t)NMAX * 4 * DMODEL];
__device__ int g_cnt   [NMAX];
__device__ int g_cur   [NMAX];
__device__ int g_rowptr[NMAX + 1];
__device__ int g_perm  [EMAX];
__device__ int g_src_s [EMAX];
__device__ int g_dst_s [EMAX];

__device__ __forceinline__ unsigned smem_u32(const void* p) {
    return (unsigned)__cvta_generic_to_shared(p);
}
__device__ __forceinline__ void cp_async16(unsigned daddr, const void* gptr, int szbytes) {
    asm volatile("cp.async.cg.shared.global [%0], [%1], 16, %2;\n"
                 :: "r"(daddr), "l"(gptr), "r"(szbytes));
}

// ---------------- init: zero CSR counters -----------------------------------
__global__ __launch_bounds__(256) void init_kernel(int Nn) {
    int i = blockIdx.x * 256 + threadIdx.x;
    if (i < Nn) { g_cnt[i] = 0; g_cur[i] = 0; }
}

// ---------------- LayerNorm: one warp per node ------------------------------
__global__ __launch_bounds__(256) void ln_kernel(const float* __restrict__ x,
                                                 const float* __restrict__ g,
                                                 const float* __restrict__ b,
                                                 float* __restrict__ out, int Nn) {
    int warp = (blockIdx.x * 256 + threadIdx.x) >> 5;
    int lane = threadIdx.x & 31;
    if (warp >= Nn) return;
    const float4* xr = (const float4*)(x + (size_t)warp * DMODEL);
    float4 a = xr[lane];
    float4 c = xr[lane + 32];
    float s = a.x + a.y + a.z + a.w + c.x + c.y + c.z + c.w;
    float q = a.x*a.x + a.y*a.y + a.z*a.z + a.w*a.w
            + c.x*c.x + c.y*c.y + c.z*c.z + c.w*c.w;
    #pragma unroll
    for (int o = 16; o; o >>= 1) {
        s += __shfl_xor_sync(0xFFFFFFFFu, s, o);
        q += __shfl_xor_sync(0xFFFFFFFFu, q, o);
    }
    float mu = s * (1.f / 256.f);
    float var = q * (1.f / 256.f) - mu * mu;
    float inv = rsqrtf(var + 1e-5f);
    float4 g0 = ((const float4*)g)[lane], g1 = ((const float4*)g)[lane + 32];
    float4 b0 = ((const float4*)b)[lane], b1 = ((const float4*)b)[lane + 32];
    float4 o0, o1;
    o0.x = (a.x - mu) * inv * g0.x + b0.x;
    o0.y = (a.y - mu) * inv * g0.y + b0.y;
    o0.z = (a.z - mu) * inv * g0.z + b0.z;
    o0.w = (a.w - mu) * inv * g0.w + b0.w;
    o1.x = (c.x - mu) * inv * g1.x + b1.x;
    o1.y = (c.y - mu) * inv * g1.y + b1.y;
    o1.z = (c.z - mu) * inv * g1.z + b1.z;
    o1.w = (c.w - mu) * inv * g1.w + b1.w;
    float4* orow = (float4*)(out + (size_t)warp * DMODEL);
    orow[lane] = o0;
    orow[lane + 32] = o1;
}

// ---------------- fold We into Wq: Wqw[n][k], bqw[n] -------------------------
__global__ __launch_bounds__(256) void prep_we_kernel(const float* __restrict__ Wq,
                                                      const float* __restrict__ bq,
                                                      const float* __restrict__ We) {
    __shared__ float sWecol[32];
    int n = blockIdx.x, h = n >> 5, i = n & 31;
    int t = threadIdx.x;
    if (t < 32) sWecol[t] = We[t * 32 + i];
    __syncthreads();
    float acc = 0.f;
    #pragma unroll
    for (int j = 0; j < 32; j++)
        acc += sWecol[j] * Wq[(size_t)(h * 32 + j) * DMODEL + t];
    g_Wqw[n * DMODEL + t] = acc;
    if (t == 0) {
        float b = 0.f;
        #pragma unroll
        for (int j = 0; j < 32; j++) b += bq[h * 32 + j] * sWecol[j];
        g_bqw[n] = b;
    }
}

// ---------------- qbe[node][h] = q[node][h,:] . be ---------------------------
__global__ __launch_bounds__(256) void qbe_kernel(const float* __restrict__ be, int Nn) {
    int node = (blockIdx.x * 256 + threadIdx.x) >> 5;
    int lane = threadIdx.x & 31;
    if (node >= Nn) return;
    float ber = be[lane];
    const float* qrow = g_q + (size_t)node * DMODEL;
    float r[NHEAD];
    #pragma unroll
    for (int h = 0; h < NHEAD; h++) {
        float p = qrow[h * 32 + lane] * ber;
        #pragma unroll
        for (int o = 16; o; o >>= 1) p += __shfl_xor_sync(0xFFFFFFFFu, p, o);
        r[h] = p;
    }
    if (lane < NHEAD) g_qbe[(size_t)node * NHEAD + lane] = r[lane];
}

// ---------------- tf32 TC GEMM core: C = epi(A @ W^T + bias) ----------------
#define TBM 128
#define TBN 128
#define TBK 32
#define SSTR 36
#define BUFW ((TBM + TBN) * SSTR)
#define SMEM_BYTES (3 * BUFW * 4)

__device__ __forceinline__ void mma_tf32(float c[4], const unsigned a[4], const unsigned b[2]) {
    asm volatile(
        "mma.sync.aligned.m16n8k8.row.col.f32.tf32.tf32.f32 "
        "{%0,%1,%2,%3},{%4,%5,%6,%7},{%8,%9},{%0,%1,%2,%3};\n"
        : "+f"(c[0]), "+f"(c[1]), "+f"(c[2]), "+f"(c[3])
        : "r"(a[0]), "r"(a[1]), "r"(a[2]), "r"(a[3]), "r"(b[0]), "r"(b[1]));
}

template <int EPI>
__device__ __forceinline__ void gemm_core(
    const float* __restrict__ A, const float* __restrict__ W,
    const float* __restrict__ bias, const float* __restrict__ R,
    const float* __restrict__ scl, float* __restrict__ C,
    int M, int N, int K, int m0, int n0) {
    extern __shared__ unsigned smem[];
    const unsigned sBase = smem_u32(smem);
    const int tid = threadIdx.x;
    const int warp = tid >> 5, lane = tid & 31;
    const int wm = warp & 3, wn = warp >> 2;
    const int g = lane >> 2, t = lane & 3;

    float acc[2][8][4];
    #pragma unroll
    for (int mi = 0; mi < 2; mi++)
        #pragma unroll
        for (int ni = 0; ni < 8; ni++)
            #pragma unroll
            for (int j = 0; j < 4; j++) acc[mi][ni][j] = 0.f;

    auto stage = [&](int buf, int k0) {
        unsigned base = sBase + (unsigned)(buf * BUFW) * 4;
        #pragma unroll
        for (int i = 0; i < 4; i++) {
            int ch = tid + i * 256;
            int r = ch >> 3, c4 = (ch & 7) * 4;
            int m = m0 + r;
            int ok = (m < M);
            const float* gp = A + (size_t)(ok ? m : 0) * K + k0 + c4;
            cp_async16(base + (unsigned)(r * SSTR + c4) * 4, gp, ok ? 16 : 0);
        }
        #pragma unroll
        for (int i = 0; i < 4; i++) {
            int ch = tid + i * 256;
            int r = ch >> 3, c4 = (ch & 7) * 4;
            const float* gp = W + (size_t)(n0 + r) * K + k0 + c4;
            cp_async16(base + (unsigned)(TBM * SSTR + r * SSTR + c4) * 4, gp, 16);
        }
        asm volatile("cp.async.commit_group;\n");
    };

    auto compute = [&](int buf) {
        const unsigned* Ab = smem + buf * BUFW;
        const unsigned* Bb = Ab + TBM * SSTR;
        #pragma unroll
        for (int ks = 0; ks < 4; ks++) {
            int k = ks * 8;
            unsigned af[2][4], bf[8][2];
            #pragma unroll
            for (int mi = 0; mi < 2; mi++) {
                int r = wm * 32 + mi * 16;
                af[mi][0] = Ab[(r + g) * SSTR + k + t];
                af[mi][1] = Ab[(r + g + 8) * SSTR + k + t];
                af[mi][2] = Ab[(r + g) * SSTR + k + t + 4];
                af[mi][3] = Ab[(r + g + 8) * SSTR + k + t + 4];
            }
            #pragma unroll
            for (int ni = 0; ni < 8; ni++) {
                int c = wn * 64 + ni * 8 + g;
                bf[ni][0] = Bb[c * SSTR + k + t];
                bf[ni][1] = Bb[c * SSTR + k + t + 4];
            }
            #pragma unroll
            for (int mi = 0; mi < 2; mi++)
                #pragma unroll
                for (int ni = 0; ni < 8; ni++)
                    mma_tf32(acc[mi][ni], af[mi], bf[ni]);
        }
    };

    const int nk = K / TBK;
    stage(0, 0);
    stage(1, TBK);
    int buf = 0;
    for (int kt = 0; kt < nk; kt++) {
        if (kt + 1 < nk) asm volatile("cp.async.wait_group 1;\n");
        else             asm volatile("cp.async.wait_group 0;\n");
        __syncthreads();
        if (kt + 2 < nk) {
            int nb = buf + 2; if (nb >= 3) nb -= 3;
            stage(nb, (kt + 2) * TBK);
        }
        compute(buf);
        if (++buf == 3) buf = 0;
    }

    float al = (EPI == 2) ? scl[0] : 0.f;
    #pragma unroll
    for (int mi = 0; mi < 2; mi++) {
        #pragma unroll
        for (int ni = 0; ni < 8; ni++) {
            int col = n0 + wn * 64 + ni * 8 + 2 * t;
            float bx = bias[col], by = bias[col + 1];
            #pragma unroll
            for (int h = 0; h < 2; h++) {
                int row = m0 + wm * 32 + mi * 16 + g + h * 8;
                if (row >= M) continue;
                float v0 = acc[mi][ni][h * 2 + 0] + bx;
                float v1 = acc[mi][ni][h * 2 + 1] + by;
                if (EPI == 1) {
                    v0 = 0.5f * v0 * (1.f + erff(v0 * 0.70710678118654752f));
                    v1 = 0.5f * v1 * (1.f + erff(v1 * 0.70710678118654752f));
                }
                if (EPI == 2) {
                    const float* rr = R + (size_t)row * N + col;
                    v0 = rr[0] + al * v0;
                    v1 = rr[1] + al * v1;
                }
                *(float2*)(C + (size_t)row * N + col) = make_float2(v0, v1);
            }
        }
    }
}

template <int EPI>
__global__ __launch_bounds__(256, 2) void gemm_tc(
    const float* __restrict__ A, const float* __restrict__ W,
    const float* __restrict__ bias, const float* __restrict__ R,
    const float* __restrict__ scl, float* __restrict__ C,
    int M, int N, int K) {
    gemm_core<EPI>(A, W, bias, R, scl, C, M, N, K,
                   blockIdx.y * TBM, blockIdx.x * TBN);
}

// fused QKV + QW: one launch, CTA selects matrix by blockIdx.x>>1 (0..3)
__global__ __launch_bounds__(256, 2) void gemm_qkv(
    const float* __restrict__ A,
    const float* __restrict__ Wq, const float* __restrict__ bq, float* __restrict__ q,
    const float* __restrict__ Wk, const float* __restrict__ bk, float* __restrict__ k,
    const float* __restrict__ Wv, const float* __restrict__ bv, float* __restrict__ v,
    const float* __restrict__ Ww, const float* __restrict__ bw, float* __restrict__ qw,
    int M) {
    int sel = blockIdx.x >> 1;
    int n0 = (blockIdx.x & 1) * TBN;
    const float* W = (sel == 0) ? Wq : (sel == 1) ? Wk : (sel == 2) ? Wv : Ww;
    const float* b = (sel == 0) ? bq : (sel == 1) ? bk : (sel == 2) ? bv : bw;
    float* C       = (sel == 0) ? q  : (sel == 1) ? k  : (sel == 2) ? v  : qw;
    gemm_core<0>(A, W, b, nullptr, nullptr, C, M, DMODEL, DMODEL,
                 blockIdx.y * TBM, n0);
}

// ---------------- CSR build --------------------------------------------------
__global__ __launch_bounds__(256) void hist_kernel(const int* __restrict__ dst, int E) {
    int i = blockIdx.x * 256 + threadIdx.x;
    if (i < E) atomicAdd(&g_cnt[dst[i]], 1);
}

__global__ __launch_bounds__(1024) void scan_kernel(int Nn, int E) {
    const int tid = threadIdx.x;
    const int lane = tid & 31, wid = tid >> 5;
    __shared__ int warp_sums[32];
    __shared__ int carry;
    if (tid == 0) carry = 0;
    __syncthreads();
    for (int base = 0; base < Nn; base += 1024) {
        int i = base + tid;
        int v = (i < Nn) ? g_cnt[i] : 0;
        int x = v;
        #pragma unroll
        for (int o = 1; o < 32; o <<= 1) {
            int y = __shfl_up_sync(0xFFFFFFFFu, x, o);
            if (lane >= o) x += y;
        }
        if (lane == 31) warp_sums[wid] = x;
        __syncthreads();
        if (wid == 0) {
            int s = warp_sums[lane];
            #pragma unroll
            for (int o = 1; o < 32; o <<= 1) {
                int y = __shfl_up_sync(0xFFFFFFFFu, s, o);
                if (lane >= o) s += y;
            }
            warp_sums[lane] = s;
        }
        __syncthreads();
        int offset = carry + (wid ? warp_sums[wid - 1] : 0);
        if (i < Nn) g_rowptr[i] = offset + x - v;
        int blocktotal = warp_sums[31];
        __syncthreads();
        if (tid == 0) carry += blocktotal;
        __syncthreads();
    }
    if (tid == 0) g_rowptr[Nn] = E;
}

__global__ __launch_bounds__(256) void scatter_kernel(const int* __restrict__ src,
                                                      const int* __restrict__ dst, int E) {
    int i = blockIdx.x * 256 + threadIdx.x;
    if (i >= E) return;
    int d = dst[i];
    int slot = g_rowptr[d] + atomicAdd(&g_cur[d], 1);
    g_perm[slot] = i;
    g_src_s[slot] = src[i];
    g_dst_s[slot] = d;
}

// ---------------- scores: warp per slot; ep folded in; coalesced lanes -------
__global__ __launch_bounds__(256) void scores_kernel(const float* __restrict__ ef,
                                                     const float* __restrict__ ew, int E) {
    __shared__ float sSc[NHEAD][8];
    int warp = threadIdx.x >> 5;
    int lane = threadIdx.x & 31;
    int slot = blockIdx.x * 8 + warp;
    if (slot < E) {
        int pe = g_perm[slot];
        int d = g_dst_s[slot];
        int s = g_src_s[slot];
        int h = lane >> 2, part = lane & 3;
        const float4* q4 = (const float4*)(g_q + (size_t)d * DMODEL + h * 32 + part * 8);
        const float4* k4 = (const float4*)(g_k + (size_t)s * DMODEL + h * 32 + part * 8);
        const float4* w4 = (const float4*)(g_qw + (size_t)d * DMODEL + h * 32 + part * 8);
        const float4* e4 = (const float4*)(ef + (size_t)pe * 32 + part * 8);
        float4 qa = q4[0], qb = q4[1];
        float4 ka = k4[0], kb = k4[1];
        float4 wa = w4[0], wb = w4[1];
        float4 ea = e4[0], eb = e4[1];
        float p = qa.x * ka.x + qa.y * ka.y + qa.z * ka.z + qa.w * ka.w
                + qb.x * kb.x + qb.y * kb.y + qb.z * kb.z + qb.w * kb.w
                + wa.x * ea.x + wa.y * ea.y + wa.z * ea.z + wa.w * ea.w
                + wb.x * eb.x + wb.y * eb.y + wb.z * eb.z + wb.w * eb.w;
        p += __shfl_xor_sync(0xFFFFFFFFu, p, 1);
        p += __shfl_xor_sync(0xFFFFFFFFu, p, 2);
        if (part == 0) {
            p += g_qbe[(size_t)d * NHEAD + h];
            sSc[h][warp] = p * ew[pe] * 0.17677669529663687f;
        }
    }
    __syncthreads();
    if (threadIdx.x < 64) {
        int h = threadIdx.x >> 3, i = threadIdx.x & 7;
        int si = blockIdx.x * 8 + i;
        if (si < E) g_sc[(size_t)h * EMAX + si] = sSc[h][i];
    }
}

// ---------------- per-node softmax + aggregate (no atomics) ------------------
__global__ __launch_bounds__(256) void node_kernel(int Nn) {
    int d = blockIdx.x;
    if (d >= Nn) return;
    int h = threadIdx.x >> 5, lane = threadIdx.x & 31;
    int b0 = g_rowptr[d], b1 = g_rowptr[d + 1];
    float* schead = g_sc + (size_t)h * EMAX;

    float m = -1e30f;
    for (int s = b0 + lane; s < b1; s += 32)
        m = fmaxf(m, schead[s]);
    #pragma unroll
    for (int o = 16; o; o >>= 1) m = fmaxf(m, __shfl_xor_sync(0xFFFFFFFFu, m, o));

    float sum = 0.f;
    for (int s = b0 + lane; s < b1; s += 32) {
        float w = __expf(schead[s] - m);
        schead[s] = w;
        sum += w;
    }
    #pragma unroll
    for (int o = 16; o; o >>= 1) sum += __shfl_xor_sync(0xFFFFFFFFu, sum, o);
    float inv = 1.f / sum;

    float a0 = 0.f, a1 = 0.f, a2 = 0.f, a3 = 0.f;
    const float* vbase = g_v + h * 32 + lane;
    for (int s0 = b0; s0 < b1; s0 += 32) {
        int n = min(32, b1 - s0);
        float w = 0.f; int sn = 0;
        if (lane < n) {
            w = schead[s0 + lane] * inv;
            sn = g_src_s[s0 + lane];
            schead[s0 + lane] = w;
        }
        int j = 0;
        for (; j + 8 <= n; j += 8) {
            float w0 = __shfl_sync(0xFFFFFFFFu, w, j + 0);
            float w1 = __shfl_sync(0xFFFFFFFFu, w, j + 1);
            float w2 = __shfl_sync(0xFFFFFFFFu, w, j + 2);
            float w3 = __shfl_sync(0xFFFFFFFFu, w, j + 3);
            float w4 = __shfl_sync(0xFFFFFFFFu, w, j + 4);
            float w5 = __shfl_sync(0xFFFFFFFFu, w, j + 5);
            float w6 = __shfl_sync(0xFFFFFFFFu, w, j + 6);
            float w7 = __shfl_sync(0xFFFFFFFFu, w, j + 7);
            int i0 = __shfl_sync(0xFFFFFFFFu, sn, j + 0);
            int i1 = __shfl_sync(0xFFFFFFFFu, sn, j + 1);
            int i2 = __shfl_sync(0xFFFFFFFFu, sn, j + 2);
            int i3 = __shfl_sync(0xFFFFFFFFu, sn, j + 3);
            int i4 = __shfl_sync(0xFFFFFFFFu, sn, j + 4);
            int i5 = __shfl_sync(0xFFFFFFFFu, sn, j + 5);
            int i6 = __shfl_sync(0xFFFFFFFFu, sn, j + 6);
            int i7 = __shfl_sync(0xFFFFFFFFu, sn, j + 7);
            a0 += w0 * vbase[(size_t)i0 * DMODEL];
            a1 += w1 * vbase[(size_t)i1 * DMODEL];
            a2 += w2 * vbase[(size_t)i2 * DMODEL];
            a3 += w3 * vbase[(size_t)i3 * DMODEL];
            a0 += w4 * vbase[(size_t)i4 * DMODEL];
            a1 += w5 * vbase[(size_t)i5 * DMODEL];
            a2 += w6 * vbase[(size_t)i6 * DMODEL];
            a3 += w7 * vbase[(size_t)i7 * DMODEL];
        }
        for (; j < n; j++) {
            float wj = __shfl_sync(0xFFFFFFFFu, w, j);
            int ij = __shfl_sync(0xFFFFFFFFu, sn, j);
            a0 += wj * vbase[(size_t)ij * DMODEL];
        }
    }
    g_agg[(size_t)d * DMODEL + h * 32 + lane] = (a0 + a1) + (a2 + a3);
}

// ---------------- permute attn weights to original edge order ----------------
__global__ __launch_bounds__(256) void attn_out_kernel(float* __restrict__ out_attn, int E) {
    int e = blockIdx.x * 256 + threadIdx.x;
    if (e >= E) return;
    int orig = g_perm[e];
    float4 w0, w1;
    w0.x = g_sc[(size_t)0 * EMAX + e];
    w0.y = g_sc[(size_t)1 * EMAX + e];
    w0.z = g_sc[(size_t)2 * EMAX + e];
    w0.w = g_sc[(size_t)3 * EMAX + e];
    w1.x = g_sc[(size_t)4 * EMAX + e];
    w1.y = g_sc[(size_t)5 * EMAX + e];
    w1.z = g_sc[(size_t)6 * EMAX + e];
    w1.w = g_sc[(size_t)7 * EMAX + e];
    float4* op = (float4*)(out_attn + (size_t)orig * NHEAD);
    op[0] = w0;
    op[1] = w1;
}

// ---------------- host launcher ---------------------------------------------
static float* sym_addr(const void* symbol) {
    void* p = nullptr;
    cudaGetSymbolAddress(&p, symbol);
    return (float*)p;
}

extern "C" void kernel_launch(void* const* d_in, const int* in_sizes, int n_in,
                              void* d_out, int out_size) {
    const float* x  = (const float*)d_in[0];
    const int*   ei = (const int*)d_in[1];
    const float* ef = (const float*)d_in[2];
    const float* ew = (const float*)d_in[3];
    const float* Wq = (const float*)d_in[4];
    const float* bq = (const float*)d_in[5];
    const float* Wk = (const float*)d_in[6];
    const float* bk = (const float*)d_in[7];
    const float* Wv = (const float*)d_in[8];
    const float* bv = (const float*)d_in[9];
    const float* We = (const float*)d_in[10];
    const float* be = (const float*)d_in[11];
    const float* Wo = (const float*)d_in[12];
    const float* bo = (const float*)d_in[13];
    const float* W1 = (const float*)d_in[14];
    const float* b1 = (const float*)d_in[15];
    const float* W2 = (const float*)d_in[16];
    const float* b2 = (const float*)d_in[17];
    const float* g1 = (const float*)d_in[18];
    const float* be1 = (const float*)d_in[19];
    const float* g2 = (const float*)d_in[20];
    const float* be2 = (const float*)d_in[21];
    const float* alpha = (const float*)d_in[22];
    const float* beta  = (const float*)d_in[23];

    int Nn = in_sizes[0] / DMODEL;
    int E  = in_sizes[1] / 2;
    const int* src = ei;
    const int* dst = ei + E;

    float* out_x    = (float*)d_out;
    float* out_attn = out_x + (size_t)Nn * DMODEL;

    float* xn  = sym_addr(g_xn);
    float* q   = sym_addr(g_q);
    float* k   = sym_addr(g_k);
    float* v   = sym_addr(g_v);
    float* qw  = sym_addr(g_qw);
    float* Wqw = sym_addr(g_Wqw);
    float* bqw = sym_addr(g_bqw);
    float* agg = sym_addr(g_agg);
    float* x1  = sym_addr(g_x1);
    float* xn2 = sym_addr(g_xn2);
    float* ff  = sym_addr(g_ff);

    cudaFuncSetAttribute(gemm_tc<1>, cudaFuncAttributeMaxDynamicSharedMemorySize, SMEM_BYTES);
    cudaFuncSetAttribute(gemm_tc<2>, cudaFuncAttributeMaxDynamicSharedMemorySize, SMEM_BYTES);
    cudaFuncSetAttribute(gemm_qkv,   cudaFuncAttributeMaxDynamicSharedMemorySize, SMEM_BYTES);

    // side stream + events (created once; per-call work identical/deterministic)
    static cudaStream_t s2 = nullptr;
    static cudaEvent_t eFork1, eJoin1, eFork2, eJoin2;
    if (!s2) {
        cudaStreamCreateWithFlags(&s2, cudaStreamNonBlocking);
        cudaEventCreateWithFlags(&eFork1, cudaEventDisableTiming);
        cudaEventCreateWithFlags(&eJoin1, cudaEventDisableTiming);
        cudaEventCreateWithFlags(&eFork2, cudaEventDisableTiming);
        cudaEventCreateWithFlags(&eJoin2, cudaEventDisableTiming);
    }

    int gy = (Nn + TBM - 1) / TBM;

    // ---- fork: CSR build on s2, node-feature pipeline on main ----
    cudaEventRecord(eFork1, 0);
    cudaStreamWaitEvent(s2, eFork1, 0);

    init_kernel<<<(Nn + 255) / 256, 256, 0, s2>>>(Nn);
    hist_kernel<<<(E + 255) / 256, 256, 0, s2>>>(dst, E);
    scan_kernel<<<1, 1024, 0, s2>>>(Nn, E);
    scatter_kernel<<<(E + 255) / 256, 256, 0, s2>>>(src, dst, E);
    cudaEventRecord(eJoin1, s2);

    ln_kernel<<<(Nn * 32 + 255) / 256, 256>>>(x, g1, be1, xn, Nn);
    prep_we_kernel<<<DMODEL, 256>>>(Wq, bq, We);
    {
        dim3 grid(8, gy);
        gemm_qkv<<<grid, 256, SMEM_BYTES>>>(xn, Wq, bq, q, Wk, bk, k, Wv, bv, v,
                                            Wqw, bqw, qw, Nn);
    }
    qbe_kernel<<<(Nn * 32 + 255) / 256, 256>>>(be, Nn);

    // ---- join: scores needs both chains ----
    cudaStreamWaitEvent(0, eJoin1, 0);
    scores_kernel<<<(E + 7) / 8, 256>>>(ef, ew, E);
    node_kernel<<<Nn, 256>>>(Nn);

    // ---- fork: attn permute on s2, Wo/FF chain on main ----
    cudaEventRecord(eFork2, 0);
    cudaStreamWaitEvent(s2, eFork2, 0);
    attn_out_kernel<<<(E + 255) / 256, 256, 0, s2>>>(out_attn, E);
    cudaEventRecord(eJoin2, s2);

    {
        dim3 grid(DMODEL / TBN, gy);
        gemm_tc<2><<<grid, 256, SMEM_BYTES>>>(agg, Wo, bo, x, alpha, x1, Nn, DMODEL, DMODEL);
    }
    ln_kernel<<<(Nn * 32 + 255) / 256, 256>>>(x1, g2, be2, xn2, Nn);
    {
        dim3 grid((4 * DMODEL) / TBN, gy);
        gemm_tc<1><<<grid, 256, SMEM_BYTES>>>(xn2, W1, b1, nullptr, nullptr, ff, Nn, 4 * DMODEL, DMODEL);
    }
    {
        dim3 grid(DMODEL / TBN, gy);
        gemm_tc<2><<<grid, 256, SMEM_BYTES>>>(ff, W2, b2, x1, beta, out_x, Nn, DMODEL, 4 * DMODEL);
    }
    cudaStreamWaitEvent(0, eJoin2, 0);
}

// round 13
// speedup vs baseline: 1.4358x; 1.4358x over previous
#include <cuda_runtime.h>
#include <cuda_bf16.h>
#include <math.h>

#define NMAX 50000
#define EMAX 1600000
#define DMODEL 256
#define NHEAD 8
#define HD 32

// ---------------- scratch (static device globals; no allocation) -------------
__device__ float g_xn  [(size_t)NMAX * DMODEL];
__device__ float g_q   [(size_t)NMAX * DMODEL];
__device__ float g_k   [(size_t)NMAX * DMODEL];
__device__ float g_v   [(size_t)NMAX * DMODEL];
__device__ float g_qw  [(size_t)NMAX * DMODEL];
__device__ float g_qbe [(size_t)NMAX * NHEAD];
__device__ float g_Wqw [DMODEL * DMODEL];
__device__ float g_bqw [DMODEL];
__device__ float g_sc  [(size_t)NHEAD * EMAX];
__device__ float g_agg [(size_t)NMAX * DMODEL];
__device__ float g_x1  [(size_t)NMAX * DMODEL];
__device__ float g_xn2 [(size_t)NMAX * DMODEL];
__device__ float g_ff  [(size_t)NMAX * 4 * DMODEL];
__device__ int g_cnt   [NMAX];
__device__ int g_rowptr[NMAX + 1];
__device__ int g_slot  [EMAX];
__device__ int g_perm  [EMAX];
__device__ int g_src_s [EMAX];
__device__ int g_dst_s [EMAX];

__device__ __forceinline__ unsigned smem_u32(const void* p) {
    return (unsigned)__cvta_generic_to_shared(p);
}
__device__ __forceinline__ void cp_async16(unsigned daddr, const void* gptr, int szbytes) {
    asm volatile("cp.async.cg.shared.global [%0], [%1], 16, %2;\n"
                 :: "r"(daddr), "l"(gptr), "r"(szbytes));
}

// ---------------- init: zero CSR counters -----------------------------------
__global__ __launch_bounds__(256) void init_kernel(int Nn) {
    int i = blockIdx.x * 256 + threadIdx.x;
    if (i < Nn) g_cnt[i] = 0;
}

// ---------------- LayerNorm: one warp per node ------------------------------
__global__ __launch_bounds__(256) void ln_kernel(const float* __restrict__ x,
                                                 const float* __restrict__ g,
                                                 const float* __restrict__ b,
                                                 float* __restrict__ out, int Nn) {
    int warp = (blockIdx.x * 256 + threadIdx.x) >> 5;
    int lane = threadIdx.x & 31;
    if (warp >= Nn) return;
    const float4* xr = (const float4*)(x + (size_t)warp * DMODEL);
    float4 a = xr[lane];
    float4 c = xr[lane + 32];
    float s = a.x + a.y + a.z + a.w + c.x + c.y + c.z + c.w;
    float q = a.x*a.x + a.y*a.y + a.z*a.z + a.w*a.w
            + c.x*c.x + c.y*c.y + c.z*c.z + c.w*c.w;
    #pragma unroll
    for (int o = 16; o; o >>= 1) {
        s += __shfl_xor_sync(0xFFFFFFFFu, s, o);
        q += __shfl_xor_sync(0xFFFFFFFFu, q, o);
    }
    float mu = s * (1.f / 256.f);
    float var = q * (1.f / 256.f) - mu * mu;
    float inv = rsqrtf(var + 1e-5f);
    float4 g0 = ((const float4*)g)[lane], g1 = ((const float4*)g)[lane + 32];
    float4 b0 = ((const float4*)b)[lane], b1 = ((const float4*)b)[lane + 32];
    float4 o0, o1;
    o0.x = (a.x - mu) * inv * g0.x + b0.x;
    o0.y = (a.y - mu) * inv * g0.y + b0.y;
    o0.z = (a.z - mu) * inv * g0.z + b0.z;
    o0.w = (a.w - mu) * inv * g0.w + b0.w;
    o1.x = (c.x - mu) * inv * g1.x + b1.x;
    o1.y = (c.y - mu) * inv * g1.y + b1.y;
    o1.z = (c.z - mu) * inv * g1.z + b1.z;
    o1.w = (c.w - mu) * inv * g1.w + b1.w;
    float4* orow = (float4*)(out + (size_t)warp * DMODEL);
    orow[lane] = o0;
    orow[lane + 32] = o1;
}

// ---------------- fold We into Wq: Wqw[n][k], bqw[n] -------------------------
__global__ __launch_bounds__(256) void prep_we_kernel(const float* __restrict__ Wq,
                                                      const float* __restrict__ bq,
                                                      const float* __restrict__ We) {
    __shared__ float sWecol[32];
    int n = blockIdx.x, h = n >> 5, i = n & 31;
    int t = threadIdx.x;
    if (t < 32) sWecol[t] = We[t * 32 + i];
    __syncthreads();
    float acc = 0.f;
    #pragma unroll
    for (int j = 0; j < 32; j++)
        acc += sWecol[j] * Wq[(size_t)(h * 32 + j) * DMODEL + t];
    g_Wqw[n * DMODEL + t] = acc;
    if (t == 0) {
        float b = 0.f;
        #pragma unroll
        for (int j = 0; j < 32; j++) b += bq[h * 32 + j] * sWecol[j];
        g_bqw[n] = b;
    }
}

// ---------------- qbe[node][h] = q[node][h,:] . be ---------------------------
__global__ __launch_bounds__(256) void qbe_kernel(const float* __restrict__ be, int Nn) {
    int node = (blockIdx.x * 256 + threadIdx.x) >> 5;
    int lane = threadIdx.x & 31;
    if (node >= Nn) return;
    float ber = be[lane];
    const float* qrow = g_q + (size_t)node * DMODEL;
    float r[NHEAD];
    #pragma unroll
    for (int h = 0; h < NHEAD; h++) {
        float p = qrow[h * 32 + lane] * ber;
        #pragma unroll
        for (int o = 16; o; o >>= 1) p += __shfl_xor_sync(0xFFFFFFFFu, p, o);
        r[h] = p;
    }
    if (lane < NHEAD) g_qbe[(size_t)node * NHEAD + lane] = r[lane];
}

// ---------------- tf32 TC GEMM core: C = epi(A @ W^T + bias) ----------------
#define TBM 128
#define TBN 128
#define TBK 32
#define SSTR 36
#define BUFW ((TBM + TBN) * SSTR)
#define SMEM_BYTES (3 * BUFW * 4)

__device__ __forceinline__ void mma_tf32(float c[4], const unsigned a[4], const unsigned b[2]) {
    asm volatile(
        "mma.sync.aligned.m16n8k8.row.col.f32.tf32.tf32.f32 "
        "{%0,%1,%2,%3},{%4,%5,%6,%7},{%8,%9},{%0,%1,%2,%3};\n"
        : "+f"(c[0]), "+f"(c[1]), "+f"(c[2]), "+f"(c[3])
        : "r"(a[0]), "r"(a[1]), "r"(a[2]), "r"(a[3]), "r"(b[0]), "r"(b[1]));
}

template <int EPI>
__device__ __forceinline__ void gemm_core(
    const float* __restrict__ A, const float* __restrict__ W,
    const float* __restrict__ bias, const float* __restrict__ R,
    const float* __restrict__ scl, float* __restrict__ C,
    int M, int N, int K, int m0, int n0) {
    extern __shared__ unsigned smem[];
    const unsigned sBase = smem_u32(smem);
    const int tid = threadIdx.x;
    const int warp = tid >> 5, lane = tid & 31;
    const int wm = warp & 3, wn = warp >> 2;
    const int g = lane >> 2, t = lane & 3;

    float acc[2][8][4];
    #pragma unroll
    for (int mi = 0; mi < 2; mi++)
        #pragma unroll
        for (int ni = 0; ni < 8; ni++)
            #pragma unroll
            for (int j = 0; j < 4; j++) acc[mi][ni][j] = 0.f;

    auto stage = [&](int buf, int k0) {
        unsigned base = sBase + (unsigned)(buf * BUFW) * 4;
        #pragma unroll
        for (int i = 0; i < 4; i++) {
            int ch = tid + i * 256;
            int r = ch >> 3, c4 = (ch & 7) * 4;
            int m = m0 + r;
            int ok = (m < M);
            const float* gp = A + (size_t)(ok ? m : 0) * K + k0 + c4;
            cp_async16(base + (unsigned)(r * SSTR + c4) * 4, gp, ok ? 16 : 0);
        }
        #pragma unroll
        for (int i = 0; i < 4; i++) {
            int ch = tid + i * 256;
            int r = ch >> 3, c4 = (ch & 7) * 4;
            const float* gp = W + (size_t)(n0 + r) * K + k0 + c4;
            cp_async16(base + (unsigned)(TBM * SSTR + r * SSTR + c4) * 4, gp, 16);
        }
        asm volatile("cp.async.commit_group;\n");
    };

    auto compute = [&](int buf) {
        const unsigned* Ab = smem + buf * BUFW;
        const unsigned* Bb = Ab + TBM * SSTR;
        #pragma unroll
        for (int ks = 0; ks < 4; ks++) {
            int k = ks * 8;
            unsigned af[2][4], bf[8][2];
            #pragma unroll
            for (int mi = 0; mi < 2; mi++) {
                int r = wm * 32 + mi * 16;
                af[mi][0] = Ab[(r + g) * SSTR + k + t];
                af[mi][1] = Ab[(r + g + 8) * SSTR + k + t];
                af[mi][2] = Ab[(r + g) * SSTR + k + t + 4];
                af[mi][3] = Ab[(r + g + 8) * SSTR + k + t + 4];
            }
            #pragma unroll
            for (int ni = 0; ni < 8; ni++) {
                int c = wn * 64 + ni * 8 + g;
                bf[ni][0] = Bb[c * SSTR + k + t];
                bf[ni][1] = Bb[c * SSTR + k + t + 4];
            }
            #pragma unroll
            for (int mi = 0; mi < 2; mi++)
                #pragma unroll
                for (int ni = 0; ni < 8; ni++)
                    mma_tf32(acc[mi][ni], af[mi], bf[ni]);
        }
    };

    const int nk = K / TBK;
    stage(0, 0);
    stage(1, TBK);
    int buf = 0;
    for (int kt = 0; kt < nk; kt++) {
        if (kt + 1 < nk) asm volatile("cp.async.wait_group 1;\n");
        else             asm volatile("cp.async.wait_group 0;\n");
        __syncthreads();
        if (kt + 2 < nk) {
            int nb = buf + 2; if (nb >= 3) nb -= 3;
            stage(nb, (kt + 2) * TBK);
        }
        compute(buf);
        if (++buf == 3) buf = 0;
    }

    float al = (EPI == 2) ? scl[0] : 0.f;
    #pragma unroll
    for (int mi = 0; mi < 2; mi++) {
        #pragma unroll
        for (int ni = 0; ni < 8; ni++) {
            int col = n0 + wn * 64 + ni * 8 + 2 * t;
            float bx = bias[col], by = bias[col + 1];
            #pragma unroll
            for (int h = 0; h < 2; h++) {
                int row = m0 + wm * 32 + mi * 16 + g + h * 8;
                if (row >= M) continue;
                float v0 = acc[mi][ni][h * 2 + 0] + bx;
                float v1 = acc[mi][ni][h * 2 + 1] + by;
                if (EPI == 1) {
                    v0 = 0.5f * v0 * (1.f + erff(v0 * 0.70710678118654752f));
                    v1 = 0.5f * v1 * (1.f + erff(v1 * 0.70710678118654752f));
                }
                if (EPI == 2) {
                    const float* rr = R + (size_t)row * N + col;
                    v0 = rr[0] + al * v0;
                    v1 = rr[1] + al * v1;
                }
                *(float2*)(C + (size_t)row * N + col) = make_float2(v0, v1);
            }
        }
    }
}

template <int EPI>
__global__ __launch_bounds__(256, 2) void gemm_tc(
    const float* __restrict__ A, const float* __restrict__ W,
    const float* __restrict__ bias, const float* __restrict__ R,
    const float* __restrict__ scl, float* __restrict__ C,
    int M, int N, int K) {
    gemm_core<EPI>(A, W, bias, R, scl, C, M, N, K,
                   blockIdx.y * TBM, blockIdx.x * TBN);
}

// fused QKV + QW: one launch, CTA selects matrix by blockIdx.x>>1 (0..3)
__global__ __launch_bounds__(256, 2) void gemm_qkv(
    const float* __restrict__ A,
    const float* __restrict__ Wq, const float* __restrict__ bq, float* __restrict__ q,
    const float* __restrict__ Wk, const float* __restrict__ bk, float* __restrict__ k,
    const float* __restrict__ Wv, const float* __restrict__ bv, float* __restrict__ v,
    const float* __restrict__ Ww, const float* __restrict__ bw, float* __restrict__ qw,
    int M) {
    int sel = blockIdx.x >> 1;
    int n0 = (blockIdx.x & 1) * TBN;
    const float* W = (sel == 0) ? Wq : (sel == 1) ? Wk : (sel == 2) ? Wv : Ww;
    const float* b = (sel == 0) ? bq : (sel == 1) ? bk : (sel == 2) ? bv : bw;
    float* C       = (sel == 0) ? q  : (sel == 1) ? k  : (sel == 2) ? v  : qw;
    gemm_core<0>(A, W, b, nullptr, nullptr, C, M, DMODEL, DMODEL,
                 blockIdx.y * TBM, n0);
}

// ---------------- CSR build --------------------------------------------------
// hist records the atomic return as the within-node slot; scatter is atomic-free.
__global__ __launch_bounds__(256) void hist_kernel(const int* __restrict__ dst, int E) {
    int i = blockIdx.x * 256 + threadIdx.x;
    if (i < E) g_slot[i] = atomicAdd(&g_cnt[dst[i]], 1);
}

__global__ __launch_bounds__(1024) void scan_kernel(int Nn, int E) {
    const int tid = threadIdx.x;
    const int lane = tid & 31, wid = tid >> 5;
    __shared__ int warp_sums[32];
    __shared__ int carry;
    if (tid == 0) carry = 0;
    __syncthreads();
    for (int base = 0; base < Nn; base += 1024) {
        int i = base + tid;
        int v = (i < Nn) ? g_cnt[i] : 0;
        int x = v;
        #pragma unroll
        for (int o = 1; o < 32; o <<= 1) {
            int y = __shfl_up_sync(0xFFFFFFFFu, x, o);
            if (lane >= o) x += y;
        }
        if (lane == 31) warp_sums[wid] = x;
        __syncthreads();
        if (wid == 0) {
            int s = warp_sums[lane];
            #pragma unroll
            for (int o = 1; o < 32; o <<= 1) {
                int y = __shfl_up_sync(0xFFFFFFFFu, s, o);
                if (lane >= o) s += y;
            }
            warp_sums[lane] = s;
        }
        __syncthreads();
        int offset = carry + (wid ? warp_sums[wid - 1] : 0);
        if (i < Nn) g_rowptr[i] = offset + x - v;
        int blocktotal = warp_sums[31];
        __syncthreads();
        if (tid == 0) carry += blocktotal;
        __syncthreads();
    }
    if (tid == 0) g_rowptr[Nn] = E;
}

__global__ __launch_bounds__(256) void scatter_kernel(const int* __restrict__ src,
                                                      const int* __restrict__ dst, int E) {
    int i = blockIdx.x * 256 + threadIdx.x;
    if (i >= E) return;
    int d = dst[i];
    int slot = g_rowptr[d] + g_slot[i];
    g_perm[slot] = i;
    g_src_s[slot] = src[i];
    g_dst_s[slot] = d;
}

// ---------------- scores: warp per slot; ep folded in; coalesced lanes -------
__global__ __launch_bounds__(256) void scores_kernel(const float* __restrict__ ef,
                                                     const float* __restrict__ ew, int E) {
    __shared__ float sSc[NHEAD][8];
    int warp = threadIdx.x >> 5;
    int lane = threadIdx.x & 31;
    int slot = blockIdx.x * 8 + warp;
    if (slot < E) {
        int pe = g_perm[slot];
        int d = g_dst_s[slot];
        int s = g_src_s[slot];
        int h = lane >> 2, part = lane & 3;
        const float4* q4 = (const float4*)(g_q + (size_t)d * DMODEL + h * 32 + part * 8);
        const float4* k4 = (const float4*)(g_k + (size_t)s * DMODEL + h * 32 + part * 8);
        const float4* w4 = (const float4*)(g_qw + (size_t)d * DMODEL + h * 32 + part * 8);
        const float4* e4 = (const float4*)(ef + (size_t)pe * 32 + part * 8);
        float4 qa = q4[0], qb = q4[1];
        float4 ka = k4[0], kb = k4[1];
        float4 wa = w4[0], wb = w4[1];
        float4 ea = e4[0], eb = e4[1];
        float p = qa.x * ka.x + qa.y * ka.y + qa.z * ka.z + qa.w * ka.w
                + qb.x * kb.x + qb.y * kb.y + qb.z * kb.z + qb.w * kb.w
                + wa.x * ea.x + wa.y * ea.y + wa.z * ea.z + wa.w * ea.w
                + wb.x * eb.x + wb.y * eb.y + wb.z * eb.z + wb.w * eb.w;
        p += __shfl_xor_sync(0xFFFFFFFFu, p, 1);
        p += __shfl_xor_sync(0xFFFFFFFFu, p, 2);
        if (part == 0) {
            p += g_qbe[(size_t)d * NHEAD + h];
            sSc[h][warp] = p * ew[pe] * 0.17677669529663687f;
        }
    }
    __syncthreads();
    if (threadIdx.x < 64) {
        int h = threadIdx.x >> 3, i = threadIdx.x & 7;
        int si = blockIdx.x * 8 + i;
        if (si < E) g_sc[(size_t)h * EMAX + si] = sSc[h][i];
    }
}

// ---------------- per-node softmax + aggregate (no atomics) ------------------
__global__ __launch_bounds__(256) void node_kernel(int Nn) {
    int d = blockIdx.x;
    if (d >= Nn) return;
    int h = threadIdx.x >> 5, lane = threadIdx.x & 31;
    int b0 = g_rowptr[d], b1 = g_rowptr[d + 1];
    float* schead = g_sc + (size_t)h * EMAX;

    float m = -1e30f;
    for (int s = b0 + lane; s < b1; s += 32)
        m = fmaxf(m, schead[s]);
    #pragma unroll
    for (int o = 16; o; o >>= 1) m = fmaxf(m, __shfl_xor_sync(0xFFFFFFFFu, m, o));

    float sum = 0.f;
    for (int s = b0 + lane; s < b1; s += 32) {
        float w = __expf(schead[s] - m);
        schead[s] = w;
        sum += w;
    }
    #pragma unroll
    for (int o = 16; o; o >>= 1) sum += __shfl_xor_sync(0xFFFFFFFFu, sum, o);
    float inv = 1.f / sum;

    float a0 = 0.f, a1 = 0.f, a2 = 0.f, a3 = 0.f;
    const float* vbase = g_v + h * 32 + lane;
    for (int s0 = b0; s0 < b1; s0 += 32) {
        int n = min(32, b1 - s0);
        float w = 0.f; int sn = 0;
        if (lane < n) {
            w = schead[s0 + lane] * inv;
            sn = g_src_s[s0 + lane];
            schead[s0 + lane] = w;
        }
        int j = 0;
        for (; j + 8 <= n; j += 8) {
            float w0 = __shfl_sync(0xFFFFFFFFu, w, j + 0);
            float w1 = __shfl_sync(0xFFFFFFFFu, w, j + 1);
            float w2 = __shfl_sync(0xFFFFFFFFu, w, j + 2);
            float w3 = __shfl_sync(0xFFFFFFFFu, w, j + 3);
            float w4 = __shfl_sync(0xFFFFFFFFu, w, j + 4);
            float w5 = __shfl_sync(0xFFFFFFFFu, w, j + 5);
            float w6 = __shfl_sync(0xFFFFFFFFu, w, j + 6);
            float w7 = __shfl_sync(0xFFFFFFFFu, w, j + 7);
            int i0 = __shfl_sync(0xFFFFFFFFu, sn, j + 0);
            int i1 = __shfl_sync(0xFFFFFFFFu, sn, j + 1);
            int i2 = __shfl_sync(0xFFFFFFFFu, sn, j + 2);
            int i3 = __shfl_sync(0xFFFFFFFFu, sn, j + 3);
            int i4 = __shfl_sync(0xFFFFFFFFu, sn, j + 4);
            int i5 = __shfl_sync(0xFFFFFFFFu, sn, j + 5);
            int i6 = __shfl_sync(0xFFFFFFFFu, sn, j + 6);
            int i7 = __shfl_sync(0xFFFFFFFFu, sn, j + 7);
            a0 += w0 * vbase[(size_t)i0 * DMODEL];
            a1 += w1 * vbase[(size_t)i1 * DMODEL];
            a2 += w2 * vbase[(size_t)i2 * DMODEL];
            a3 += w3 * vbase[(size_t)i3 * DMODEL];
            a0 += w4 * vbase[(size_t)i4 * DMODEL];
            a1 += w5 * vbase[(size_t)i5 * DMODEL];
            a2 += w6 * vbase[(size_t)i6 * DMODEL];
            a3 += w7 * vbase[(size_t)i7 * DMODEL];
        }
        for (; j < n; j++) {
            float wj = __shfl_sync(0xFFFFFFFFu, w, j);
            int ij = __shfl_sync(0xFFFFFFFFu, sn, j);
            a0 += wj * vbase[(size_t)ij * DMODEL];
        }
    }
    g_agg[(size_t)d * DMODEL + h * 32 + lane] = (a0 + a1) + (a2 + a3);
}

// ---------------- permute attn weights to original edge order ----------------
__global__ __launch_bounds__(256) void attn_out_kernel(float* __restrict__ out_attn, int E) {
    int e = blockIdx.x * 256 + threadIdx.x;
    if (e >= E) return;
    int orig = g_perm[e];
    float4 w0, w1;
    w0.x = g_sc[(size_t)0 * EMAX + e];
    w0.y = g_sc[(size_t)1 * EMAX + e];
    w0.z = g_sc[(size_t)2 * EMAX + e];
    w0.w = g_sc[(size_t)3 * EMAX + e];
    w1.x = g_sc[(size_t)4 * EMAX + e];
    w1.y = g_sc[(size_t)5 * EMAX + e];
    w1.z = g_sc[(size_t)6 * EMAX + e];
    w1.w = g_sc[(size_t)7 * EMAX + e];
    float4* op = (float4*)(out_attn + (size_t)orig * NHEAD);
    op[0] = w0;
    op[1] = w1;
}

// ---------------- host launcher ---------------------------------------------
static float* sym_addr(const void* symbol) {
    void* p = nullptr;
    cudaGetSymbolAddress(&p, symbol);
    return (float*)p;
}

extern "C" void kernel_launch(void* const* d_in, const int* in_sizes, int n_in,
                              void* d_out, int out_size) {
    const float* x  = (const float*)d_in[0];
    const int*   ei = (const int*)d_in[1];
    const float* ef = (const float*)d_in[2];
    const float* ew = (const float*)d_in[3];
    const float* Wq = (const float*)d_in[4];
    const float* bq = (const float*)d_in[5];
    const float* Wk = (const float*)d_in[6];
    const float* bk = (const float*)d_in[7];
    const float* Wv = (const float*)d_in[8];
    const float* bv = (const float*)d_in[9];
    const float* We = (const float*)d_in[10];
    const float* be = (const float*)d_in[11];
    const float* Wo = (const float*)d_in[12];
    const float* bo = (const float*)d_in[13];
    const float* W1 = (const float*)d_in[14];
    const float* b1 = (const float*)d_in[15];
    const float* W2 = (const float*)d_in[16];
    const float* b2 = (const float*)d_in[17];
    const float* g1 = (const float*)d_in[18];
    const float* be1 = (const float*)d_in[19];
    const float* g2 = (const float*)d_in[20];
    const float* be2 = (const float*)d_in[21];
    const float* alpha = (const float*)d_in[22];
    const float* beta  = (const float*)d_in[23];

    int Nn = in_sizes[0] / DMODEL;
    int E  = in_sizes[1] / 2;
    const int* src = ei;
    const int* dst = ei + E;

    float* out_x    = (float*)d_out;
    float* out_attn = out_x + (size_t)Nn * DMODEL;

    float* xn  = sym_addr(g_xn);
    float* q   = sym_addr(g_q);
    float* k   = sym_addr(g_k);
    float* v   = sym_addr(g_v);
    float* qw  = sym_addr(g_qw);
    float* Wqw = sym_addr(g_Wqw);
    float* bqw = sym_addr(g_bqw);
    float* agg = sym_addr(g_agg);
    float* x1  = sym_addr(g_x1);
    float* xn2 = sym_addr(g_xn2);
    float* ff  = sym_addr(g_ff);

    cudaFuncSetAttribute(gemm_tc<1>, cudaFuncAttributeMaxDynamicSharedMemorySize, SMEM_BYTES);
    cudaFuncSetAttribute(gemm_tc<2>, cudaFuncAttributeMaxDynamicSharedMemorySize, SMEM_BYTES);
    cudaFuncSetAttribute(gemm_qkv,   cudaFuncAttributeMaxDynamicSharedMemorySize, SMEM_BYTES);

    int gy = (Nn + TBM - 1) / TBM;

    init_kernel<<<(Nn + 255) / 256, 256>>>(Nn);
    ln_kernel<<<(Nn * 32 + 255) / 256, 256>>>(x, g1, be1, xn, Nn);
    prep_we_kernel<<<DMODEL, 256>>>(Wq, bq, We);
    {
        dim3 grid(8, gy);
        gemm_qkv<<<grid, 256, SMEM_BYTES>>>(xn, Wq, bq, q, Wk, bk, k, Wv, bv, v,
                                            Wqw, bqw, qw, Nn);
    }
    qbe_kernel<<<(Nn * 32 + 255) / 256, 256>>>(be, Nn);
    hist_kernel<<<(E + 255) / 256, 256>>>(dst, E);
    scan_kernel<<<1, 1024>>>(Nn, E);
    scatter_kernel<<<(E + 255) / 256, 256>>>(src, dst, E);
    scores_kernel<<<(E + 7) / 8, 256>>>(ef, ew, E);
    node_kernel<<<Nn, 256>>>(Nn);
    attn_out_kernel<<<(E + 255) / 256, 256>>>(out_attn, E);
    {
        dim3 grid(DMODEL / TBN, gy);
        gemm_tc<2><<<grid, 256, SMEM_BYTES>>>(agg, Wo, bo, x, alpha, x1, Nn, DMODEL, DMODEL);
    }
    ln_kernel<<<(Nn * 32 + 255) / 256, 256>>>(x1, g2, be2, xn2, Nn);
    {
        dim3 grid((4 * DMODEL) / TBN, gy);
        gemm_tc<1><<<grid, 256, SMEM_BYTES>>>(xn2, W1, b1, nullptr, nullptr, ff, Nn, 4 * DMODEL, DMODEL);
    }
    {
        dim3 grid(DMODEL / TBN, gy);
        gemm_tc<2><<<grid, 256, SMEM_BYTES>>>(ff, W2, b2, x1, beta, out_x, Nn, DMODEL, 4 * DMODEL);
    }
}